// round 6
// baseline (speedup 1.0000x reference)
#include <cuda_runtime.h>
#include <cuda_bf16.h>

// TokenCombiner: out[r] = inp[in_off[j] + (r - out_off[j])] for the chunk j
// owning output row r (out_off sorted ascending); rows past a chunk's split
// keep the original `out` buffer value.
//
// Inputs (metadata order):
//   d_in[0] : float32 inp  [IN_LEN * HIDDEN]
//   d_in[1] : float32 out  [OUT_LEN * HIDDEN]  (fallback values for padding rows)
//   d_in[2] : int32 in_splits_offsets  [2, NSPLITS]
//   d_in[3] : int32 out_splits_offsets [2, NSPLITS]
// Output: float32 [OUT_LEN * HIDDEN]
//
// Persistent single-wave kernel: 148 SMs x 6 CTAs, grid-stride over row pairs.

#ifndef HIDDEN_F32
#define HIDDEN_F32 4096
#endif
#define VEC_PER_ROW (HIDDEN_F32 / 4)   // 1024 float4 per row
#define LOG2_VPR 10
#define MAX_SPLITS 64
#define THREADS 256
#define ROWS_PER_ITER 2                // 2 rows * 1024 f4 per grid-stride step
#define F4_PER_ROW_PER_THREAD (VEC_PER_ROW / THREADS)  // 4
#define NUM_SMS 148
#define CTAS_PER_SM 6

__global__ __launch_bounds__(THREADS)
void token_combine_kernel(
    const float4* __restrict__ inp,
    const float4* __restrict__ outbuf,
    const int* __restrict__ in_so,    // [2, nsplits] int32
    const int* __restrict__ out_so,   // [2, nsplits] int32
    float4* __restrict__ out,
    int nsplits,
    int nrows)
{
    __shared__ int s_in_off[MAX_SPLITS];
    __shared__ int s_out_split[MAX_SPLITS];
    __shared__ int s_out_off[MAX_SPLITS];

    if (threadIdx.x < nsplits) {
        s_in_off[threadIdx.x]    = in_so[nsplits + threadIdx.x];
        s_out_split[threadIdx.x] = out_so[threadIdx.x];
        s_out_off[threadIdx.x]   = out_so[nsplits + threadIdx.x];
    }
    __syncthreads();

    const unsigned t = threadIdx.x;
    const unsigned row_step = gridDim.x * ROWS_PER_ITER;

    for (unsigned row0 = blockIdx.x * ROWS_PER_ITER; row0 < (unsigned)nrows;
         row0 += row_step) {

        // Resolve the source pointer base ONCE per row (warp-uniform).
        const float4* src_ptr[ROWS_PER_ITER];
        #pragma unroll
        for (int r = 0; r < ROWS_PER_ITER; r++) {
            unsigned row = row0 + r;
            int j = 0;
            #pragma unroll 8
            for (int q = 1; q < nsplits; q++) {
                if ((unsigned)s_out_off[q] <= row) j = q;
            }
            unsigned pos = row - (unsigned)s_out_off[j];
            bool valid = pos < (unsigned)s_out_split[j];
            unsigned src_row = (unsigned)s_in_off[j] + pos;
            unsigned src_off = valid ? (src_row << LOG2_VPR) : (row << LOG2_VPR);
            const float4* base = valid ? inp : outbuf;
            src_ptr[r] = base + src_off + t;
        }

        // Front-batched loads: 8 independent LDG.128 (streaming — no reuse).
        float4 v[ROWS_PER_ITER][F4_PER_ROW_PER_THREAD];
        #pragma unroll
        for (int r = 0; r < ROWS_PER_ITER; r++) {
            #pragma unroll
            for (int k = 0; k < F4_PER_ROW_PER_THREAD; k++) {
                v[r][k] = __ldcs(src_ptr[r] + k * THREADS);
            }
        }

        // Streaming stores (fire-and-forget; next iter's loads overlap).
        float4* dst = out + (row0 << LOG2_VPR) + t;
        #pragma unroll
        for (int r = 0; r < ROWS_PER_ITER; r++) {
            #pragma unroll
            for (int k = 0; k < F4_PER_ROW_PER_THREAD; k++) {
                __stcs(dst + (unsigned)(r * VEC_PER_ROW + k * THREADS), v[r][k]);
            }
        }
    }
}

extern "C" void kernel_launch(void* const* d_in, const int* in_sizes, int n_in,
                              void* d_out, int out_size)
{
    const float4* inp    = (const float4*)d_in[0];
    const float4* outbuf = (const float4*)d_in[1];
    const int* in_so  = (const int*)d_in[2];
    const int* out_so = (const int*)d_in[3];
    float4* out = (float4*)d_out;

    int nsplits = in_sizes[2] / 2;
    int total_vec = out_size / 4;                  // float4 count
    int nrows = total_vec >> LOG2_VPR;             // rows of 1024 float4

    int blocks = NUM_SMS * CTAS_PER_SM;            // one full wave
    int max_blocks = (nrows + ROWS_PER_ITER - 1) / ROWS_PER_ITER;
    if (blocks > max_blocks) blocks = max_blocks;

    token_combine_kernel<<<blocks, THREADS>>>(
        inp, outbuf, in_so, out_so, out, nsplits, nrows);
}

// round 7
// speedup vs baseline: 1.0759x; 1.0759x over previous
#include <cuda_runtime.h>
#include <cuda_bf16.h>

// TokenCombiner: out[r] = inp[in_off[j] + (r - out_off[j])] for the chunk j
// owning output row r (out_off sorted ascending); rows past a chunk's split
// keep the original `out` buffer value.
//
// Inputs (metadata order):
//   d_in[0] : float32 inp  [IN_LEN * HIDDEN]
//   d_in[1] : float32 out  [OUT_LEN * HIDDEN]  (fallback values for padding rows)
//   d_in[2] : int32 in_splits_offsets  [2, NSPLITS]
//   d_in[3] : int32 out_splits_offsets [2, NSPLITS]
// Output: float32 [OUT_LEN * HIDDEN]
//
// High-occupancy variant: 1 row in flight at a time (16 data regs),
// __launch_bounds__(256, 8) -> <=32 regs -> 8 CTAs/SM (100% occ).

#ifndef HIDDEN_F32
#define HIDDEN_F32 4096
#endif
#define VEC_PER_ROW (HIDDEN_F32 / 4)   // 1024 float4 per row
#define LOG2_VPR 10
#define MAX_SPLITS 64
#define THREADS 256
#define ROWS_PER_BLOCK 2               // 2 rows, processed one at a time
#define F4_PER_ROW_PER_THREAD (VEC_PER_ROW / THREADS)  // 4

__global__ __launch_bounds__(THREADS, 8)
void token_combine_kernel(
    const float4* __restrict__ inp,
    const float4* __restrict__ outbuf,
    const int* __restrict__ in_so,    // [2, nsplits] int32
    const int* __restrict__ out_so,   // [2, nsplits] int32
    float4* __restrict__ out,
    int nsplits,
    int nrows)
{
    __shared__ int s_in_off[MAX_SPLITS];
    __shared__ int s_out_split[MAX_SPLITS];
    __shared__ int s_out_off[MAX_SPLITS];

    if (threadIdx.x < nsplits) {
        s_in_off[threadIdx.x]    = in_so[nsplits + threadIdx.x];
        s_out_split[threadIdx.x] = out_so[threadIdx.x];
        s_out_off[threadIdx.x]   = out_so[nsplits + threadIdx.x];
    }
    __syncthreads();

    const unsigned t = threadIdx.x;
    const unsigned row0 = blockIdx.x * ROWS_PER_BLOCK;

    #pragma unroll
    for (int r = 0; r < ROWS_PER_BLOCK; r++) {
        unsigned row = row0 + r;

        // Resolve source row once (warp-uniform; nsplits tiny).
        int j = 0;
        #pragma unroll 8
        for (int q = 1; q < nsplits; q++) {
            if ((unsigned)s_out_off[q] <= row) j = q;
        }
        unsigned pos = row - (unsigned)s_out_off[j];
        bool valid = pos < (unsigned)s_out_split[j];
        unsigned src_row = (unsigned)s_in_off[j] + pos;
        unsigned src_off = valid ? (src_row << LOG2_VPR) : (row << LOG2_VPR);
        const float4* src = (valid ? inp : outbuf) + src_off + t;
        float4* dst = out + (row << LOG2_VPR) + t;

        // 4 independent LDG.128, then 4 STG.128 (streaming, no reuse).
        float4 v0 = __ldcs(src + 0 * THREADS);
        float4 v1 = __ldcs(src + 1 * THREADS);
        float4 v2 = __ldcs(src + 2 * THREADS);
        float4 v3 = __ldcs(src + 3 * THREADS);
        __stcs(dst + 0 * THREADS, v0);
        __stcs(dst + 1 * THREADS, v1);
        __stcs(dst + 2 * THREADS, v2);
        __stcs(dst + 3 * THREADS, v3);
    }
}

extern "C" void kernel_launch(void* const* d_in, const int* in_sizes, int n_in,
                              void* d_out, int out_size)
{
    const float4* inp    = (const float4*)d_in[0];
    const float4* outbuf = (const float4*)d_in[1];
    const int* in_so  = (const int*)d_in[2];
    const int* out_so = (const int*)d_in[3];
    float4* out = (float4*)d_out;

    int nsplits = in_sizes[2] / 2;
    int total_vec = out_size / 4;                  // float4 count
    int nrows = total_vec >> LOG2_VPR;             // rows of 1024 float4

    int blocks = (nrows + ROWS_PER_BLOCK - 1) / ROWS_PER_BLOCK;

    token_combine_kernel<<<blocks, THREADS>>>(
        inp, outbuf, in_so, out_so, out, nsplits, nrows);
}